// round 2
// baseline (speedup 1.0000x reference)
#include <cuda_runtime.h>
#include <math_constants.h>

#define BB 8
#define CC 256
#define NN 4096

// Scratch (allocation-free rule: __device__ globals)
__device__ float g_Gt[CC * CC];       // Gt[e*CC + c] = G[c,e] = sum_d Wq[d,c]*Wk[d,e]
__device__ float g_Z[BB * CC * NN];   // z[b,c,m] = sum_e G[c,e] * feat[b,e,m]

// ---------------------------------------------------------------------------
// Kernel A: Gt[e][c] = sum_d Wq[d][c] * Wk[d][e]   (tiny: 16.7M MACs)
// ---------------------------------------------------------------------------
__global__ void k_gt(const float* __restrict__ Wq, const float* __restrict__ Wk) {
    const int e = blockIdx.x;
    const int c = threadIdx.x;
    float acc = 0.f;
#pragma unroll 8
    for (int d = 0; d < CC; d++) {
        acc += Wq[d * CC + c] * Wk[d * CC + e];   // Wq coalesced over c, Wk broadcast
    }
    g_Gt[e * CC + c] = acc;
}

// ---------------------------------------------------------------------------
// Kernel B: z[b,c,m] = sum_e Gt[e][c] * feat[b,e,m]
// 128x128 tile, K=256, double-buffered, 8x8 micro-tiles.
// grid = (NN/128, CC/128, BB)
// ---------------------------------------------------------------------------
__global__ void __launch_bounds__(256, 2) k_z(const float* __restrict__ feat) {
    const int m0 = blockIdx.x * 128;
    const int c0 = blockIdx.y * 128;
    const int b  = blockIdx.z;

    const float* A  = g_Gt;                 // [e][c], K-major
    const float* Bp = feat + b * CC * NN;   // [e][m], K-major
    float*       Zp = g_Z  + b * CC * NN;

    __shared__ float As[2][8][128];
    __shared__ float Bs[2][8][128];

    const int tid = threadIdx.x;
    const int tx = tid & 15;        // m micro-tile index
    const int ty = tid >> 4;        // c micro-tile index
    const int lr = tid >> 5;        // load row 0..7
    const int lc = (tid & 31) * 4;  // load col 0..124

    float acc[8][8];
#pragma unroll
    for (int i = 0; i < 8; i++)
#pragma unroll
        for (int j = 0; j < 8; j++) acc[i][j] = 0.f;

    // preload chunk 0
    {
        float4 ra = *(const float4*)&A [(0 + lr) * CC + c0 + lc];
        float4 rb = *(const float4*)&Bp[(0 + lr) * NN + m0 + lc];
        *(float4*)&As[0][lr][lc] = ra;
        *(float4*)&Bs[0][lr][lc] = rb;
    }
    __syncthreads();

    int cur = 0;
    for (int kt = 0; kt < 32; kt++) {
        float4 ra, rb;
        if (kt < 31) {
            const int k = (kt + 1) * 8;
            ra = *(const float4*)&A [(k + lr) * CC + c0 + lc];
            rb = *(const float4*)&Bp[(k + lr) * NN + m0 + lc];
        }
#pragma unroll
        for (int kk = 0; kk < 8; kk++) {
            float av[8], bv[8];
            *(float4*)(av)     = *(const float4*)&As[cur][kk][ty * 8];
            *(float4*)(av + 4) = *(const float4*)&As[cur][kk][ty * 8 + 4];
            *(float4*)(bv)     = *(const float4*)&Bs[cur][kk][tx * 8];
            *(float4*)(bv + 4) = *(const float4*)&Bs[cur][kk][tx * 8 + 4];
#pragma unroll
            for (int i = 0; i < 8; i++)
#pragma unroll
                for (int j = 0; j < 8; j++) acc[i][j] += av[i] * bv[j];
        }
        if (kt < 31) {
            *(float4*)&As[cur ^ 1][lr][lc] = ra;
            *(float4*)&Bs[cur ^ 1][lr][lc] = rb;
            __syncthreads();
            cur ^= 1;
        }
    }

#pragma unroll
    for (int i = 0; i < 8; i++) {
        const int c = c0 + ty * 8 + i;
        *(float4*)&Zp[c * NN + m0 + tx * 8]     = *(float4*)&acc[i][0];
        *(float4*)&Zp[c * NN + m0 + tx * 8 + 4] = *(float4*)&acc[i][4];
    }
}

// ---------------------------------------------------------------------------
// Kernel C: streaming logits + online softmax diagonal + output scale.
// Each block: 128 rows (n) of one batch; loops over all 32 m-tiles.
// logits[n,m] = sum_c feat[b,c,n] * z[b,c,m]
// grid = (NN/128, BB)
// ---------------------------------------------------------------------------
__global__ void __launch_bounds__(256, 2) k_attn(const float* __restrict__ feat,
                                                 float* __restrict__ out) {
    const int n0 = blockIdx.x * 128;
    const int b  = blockIdx.y;

    const float* F  = feat + b * CC * NN;   // [c][n], K-major
    const float* Zp = g_Z  + b * CC * NN;   // [c][m], K-major

    __shared__ float As[2][8][128];
    __shared__ float Bs[2][8][128];
    __shared__ float sDiagLogit[128];
    __shared__ float sDiag[128];

    const int tid = threadIdx.x;
    const int tx = tid & 15;
    const int ty = tid >> 4;
    const int lr = tid >> 5;
    const int lc = (tid & 31) * 4;

    float run_m[8], run_l[8];
#pragma unroll
    for (int i = 0; i < 8; i++) { run_m[i] = -CUDART_INF_F; run_l[i] = 0.f; }

    for (int mt = 0; mt < 32; mt++) {
        const int m0 = mt * 128;

        float acc[8][8];
#pragma unroll
        for (int i = 0; i < 8; i++)
#pragma unroll
            for (int j = 0; j < 8; j++) acc[i][j] = 0.f;

        // preload chunk 0 into buffer 0 (safe: laggards only touch buffer 1 here)
        {
            float4 ra = *(const float4*)&F [(0 + lr) * NN + n0 + lc];
            float4 rb = *(const float4*)&Zp[(0 + lr) * NN + m0 + lc];
            *(float4*)&As[0][lr][lc] = ra;
            *(float4*)&Bs[0][lr][lc] = rb;
        }
        __syncthreads();

        int cur = 0;
        for (int kt = 0; kt < 32; kt++) {
            float4 ra, rb;
            if (kt < 31) {
                const int k = (kt + 1) * 8;
                ra = *(const float4*)&F [(k + lr) * NN + n0 + lc];
                rb = *(const float4*)&Zp[(k + lr) * NN + m0 + lc];
            }
#pragma unroll
            for (int kk = 0; kk < 8; kk++) {
                float av[8], bv[8];
                *(float4*)(av)     = *(const float4*)&As[cur][kk][ty * 8];
                *(float4*)(av + 4) = *(const float4*)&As[cur][kk][ty * 8 + 4];
                *(float4*)(bv)     = *(const float4*)&Bs[cur][kk][tx * 8];
                *(float4*)(bv + 4) = *(const float4*)&Bs[cur][kk][tx * 8 + 4];
#pragma unroll
                for (int i = 0; i < 8; i++)
#pragma unroll
                    for (int j = 0; j < 8; j++) acc[i][j] += av[i] * bv[j];
            }
            if (kt < 31) {
                *(float4*)&As[cur ^ 1][lr][lc] = ra;
                *(float4*)&Bs[cur ^ 1][lr][lc] = rb;
                __syncthreads();
                cur ^= 1;
            }
        }

        // ---- online softmax update (rows shared by the 16 tx-threads; they are
        //      lanes (ty&1)*16 + 0..15 of one warp -> xor-shuffles of 1,2,4,8) ----
#pragma unroll
        for (int i = 0; i < 8; i++) {
            const int n = n0 + ty * 8 + i;

            float mx = acc[i][0];
#pragma unroll
            for (int j = 1; j < 8; j++) mx = fmaxf(mx, acc[i][j]);
#pragma unroll
            for (int off = 1; off < 16; off <<= 1)
                mx = fmaxf(mx, __shfl_xor_sync(0xffffffffu, mx, off));

            const float nm = fmaxf(run_m[i], mx);
            float s = 0.f;
#pragma unroll
            for (int j = 0; j < 8; j++) s += __expf(acc[i][j] - nm);
#pragma unroll
            for (int off = 1; off < 16; off <<= 1)
                s += __shfl_xor_sync(0xffffffffu, s, off);

            run_l[i] = run_l[i] * __expf(run_m[i] - nm) + s;
            run_m[i] = nm;

            // capture raw diagonal logit when its tile passes by
            const int dcol = n - m0;
            if (dcol >= tx * 8 && dcol < tx * 8 + 8)
                sDiagLogit[ty * 8 + i] = acc[i][dcol - tx * 8];
        }
        // no extra sync needed: double-buffer argument covers the next preload
    }

    __syncthreads();
    if (tx == 0) {
#pragma unroll
        for (int i = 0; i < 8; i++) {
            const int r = ty * 8 + i;
            sDiag[r] = __expf(sDiagLogit[r] - run_m[i]) / run_l[i];
        }
    }
    __syncthreads();

    // out[b,c,n0+j] = feat[b,c,n0+j] * diag[n0+j]
    float* O = out + b * CC * NN;
    for (int idx = tid; idx < CC * 128; idx += 256) {
        const int c = idx >> 7;
        const int j = idx & 127;
        O[c * NN + n0 + j] = F[c * NN + n0 + j] * sDiag[j];
    }
}

// ---------------------------------------------------------------------------
extern "C" void kernel_launch(void* const* d_in, const int* in_sizes, int n_in,
                              void* d_out, int out_size) {
    const float* feat = (const float*)d_in[0];  // [B,C,N]
    const float* Wq   = (const float*)d_in[1];  // [C,C]
    const float* Wk   = (const float*)d_in[2];  // [C,C]
    float* out = (float*)d_out;                 // [B,C,N]

    k_gt<<<CC, CC>>>(Wq, Wk);

    dim3 gz(NN / 128, CC / 128, BB);
    k_z<<<gz, 256>>>(feat);

    dim3 ga(NN / 128, BB);
    k_attn<<<ga, 256>>>(feat, out);
}

// round 5
// speedup vs baseline: 7.4794x; 7.4794x over previous
#include <cuda_runtime.h>
#include <cuda_bf16.h>
#include <cstdint>
#include <math_constants.h>

#define BB 8
#define CC 256
#define NN 4096

// ---------------- device scratch (allocation-free rule) ----------------
__device__ __nv_bfloat16 g_Ft_hi[BB * NN * CC];   // feat^T [b][n][c]
__device__ __nv_bfloat16 g_Ft_lo[BB * NN * CC];
__device__ __nv_bfloat16 g_Zt_hi[BB * NN * CC];   // Z^T [b][m][c]
__device__ __nv_bfloat16 g_Zt_lo[BB * NN * CC];
__device__ __nv_bfloat16 g_Gk_hi[CC * CC];        // G [c][e]
__device__ __nv_bfloat16 g_Gk_lo[CC * CC];

// ---------------- SMEM layout ----------------
#define CH       16384                 // one 128x64 bf16 chunk, SW128 swizzled
#define OFF_A    0                     // 8 chunks (hi:0..3, lo:4..7) = 131072
#define OFF_B    131072                // 2 bufs x (hi+lo) = 2*32768
#define BUFSZ    32768
#define OFF_EPI  196608
#define EP_RUNM  (OFF_EPI + 0)
#define EP_RUNL  (OFF_EPI + 512)
#define EP_REDA  (OFF_EPI + 1024)
#define EP_REDB  (OFF_EPI + 2048)
#define EP_NEWM  (OFF_EPI + 3072)
#define EP_DLOG  (OFF_EPI + 3584)
#define EP_DIAG  (OFF_EPI + 4096)
#define SMEM_TOTAL 201216

__device__ __forceinline__ uint32_t smem_u32(const void* p) {
    uint32_t a;
    asm("{ .reg .u64 t; cvta.to.shared.u64 t, %1; cvt.u32.u64 %0, t; }" : "=r"(a) : "l"(p));
    return a;
}

#define CPA_COMMIT() asm volatile("cp.async.commit_group;" ::: "memory")
#define CPA_WAIT0()  asm volatile("cp.async.wait_group 0;" ::: "memory")

// 128 rows x 64 bf16 chunk (gmem row stride CC) -> SW128 swizzled smem, cp.async
__device__ __forceinline__ void cpa_chunk(uint32_t dst, const __nv_bfloat16* g, int tid) {
#pragma unroll
    for (int it = 0; it < 4; it++) {
        int u = tid + it * 256;
        int row = u >> 3, seg = u & 7;
        uint32_t bo = (uint32_t)(row * 128 + seg * 16);
        bo ^= ((bo >> 3) & 0x70);
        asm volatile("cp.async.cg.shared.global [%0], [%1], 16;"
                     :: "r"(dst + bo), "l"((const void*)(g + row * CC + seg * 8)) : "memory");
    }
}

// same, but synchronous LDG/STS (used once for the resident A tile)
__device__ __forceinline__ void copy_chunk(char* sm, uint32_t dst, const __nv_bfloat16* g, int tid) {
#pragma unroll
    for (int it = 0; it < 4; it++) {
        int u = tid + it * 256;
        int row = u >> 3, seg = u & 7;
        uint4 v = *(const uint4*)(g + row * CC + seg * 8);
        uint32_t bo = (uint32_t)(row * 128 + seg * 16);
        bo ^= ((bo >> 3) & 0x70);
        *(uint4*)(sm + dst + bo) = v;
    }
}

__device__ __forceinline__ void ldsm4(uint32_t addr, uint32_t r[4]) {
    asm volatile("ldmatrix.sync.aligned.m8n8.x4.shared.b16 {%0,%1,%2,%3}, [%4];"
                 : "=r"(r[0]), "=r"(r[1]), "=r"(r[2]), "=r"(r[3]) : "r"(addr));
}

__device__ __forceinline__ void mma16816(float d[4], const uint32_t a[4], uint32_t b0, uint32_t b1) {
    asm volatile("mma.sync.aligned.m16n8k16.row.col.f32.bf16.bf16.f32 "
                 "{%0,%1,%2,%3}, {%4,%5,%6,%7}, {%8,%9}, {%0,%1,%2,%3};"
                 : "+f"(d[0]), "+f"(d[1]), "+f"(d[2]), "+f"(d[3])
                 : "r"(a[0]), "r"(a[1]), "r"(a[2]), "r"(a[3]), "r"(b0), "r"(b1));
}

// One 64-c k-chunk: acc += Ah*Bh + Ah*Bl + Al*Bh for a 32x64 warp tile.
__device__ __forceinline__ void mma_kchunk(uint32_t aH, uint32_t aL, uint32_t bH, uint32_t bL,
                                           uint32_t aro0, const uint32_t* bro,
                                           uint32_t lhi, uint32_t xorv, float acc[2][8][4]) {
#pragma unroll
    for (int ks = 0; ks < 4; ks++) {
        uint32_t cx = ((uint32_t)(ks * 32) + lhi) ^ xorv;
        uint32_t ah0[4], ah1[4], al0[4], al1[4];
        ldsm4(aH + aro0 + cx, ah0);
        ldsm4(aH + aro0 + 2048 + cx, ah1);
        ldsm4(aL + aro0 + cx, al0);
        ldsm4(aL + aro0 + 2048 + cx, al1);
#pragma unroll
        for (int g16 = 0; g16 < 4; g16++) {
            uint32_t bh[4], bl[4];
            ldsm4(bH + bro[g16] + cx, bh);
            ldsm4(bL + bro[g16] + cx, bl);
            const int g0 = 2 * g16, g1 = 2 * g16 + 1;
            mma16816(acc[0][g0], ah0, bh[0], bh[2]);
            mma16816(acc[1][g0], ah1, bh[0], bh[2]);
            mma16816(acc[0][g1], ah0, bh[1], bh[3]);
            mma16816(acc[1][g1], ah1, bh[1], bh[3]);
            mma16816(acc[0][g0], ah0, bl[0], bl[2]);
            mma16816(acc[1][g0], ah1, bl[0], bl[2]);
            mma16816(acc[0][g1], ah0, bl[1], bl[3]);
            mma16816(acc[1][g1], ah1, bl[1], bl[3]);
            mma16816(acc[0][g0], al0, bh[0], bh[2]);
            mma16816(acc[1][g0], al1, bh[0], bh[2]);
            mma16816(acc[0][g1], al0, bh[1], bh[3]);
            mma16816(acc[1][g1], al1, bh[1], bh[3]);
        }
    }
}

// ---------------------------------------------------------------------------
// k_gt: G[c][e] = sum_d Wq[d][c]*Wk[d][e], bf16 hi/lo. grid 128, block 256.
// ---------------------------------------------------------------------------
__global__ void k_gt(const float* __restrict__ Wq, const float* __restrict__ Wk) {
    __shared__ float sq[2][CC];
    const int c0 = blockIdx.x * 2, e = threadIdx.x;
    sq[0][e] = Wq[e * CC + c0];
    sq[1][e] = Wq[e * CC + c0 + 1];
    __syncthreads();
    float a0 = 0.f, a1 = 0.f;
#pragma unroll 8
    for (int d = 0; d < CC; d++) {
        float wk = Wk[d * CC + e];
        a0 += sq[0][d] * wk;
        a1 += sq[1][d] * wk;
    }
    __nv_bfloat16 h0 = __float2bfloat16(a0), h1 = __float2bfloat16(a1);
    g_Gk_hi[c0 * CC + e] = h0;
    g_Gk_lo[c0 * CC + e] = __float2bfloat16(a0 - __bfloat162float(h0));
    g_Gk_hi[(c0 + 1) * CC + e] = h1;
    g_Gk_lo[(c0 + 1) * CC + e] = __float2bfloat16(a1 - __bfloat162float(h1));
}

// ---------------------------------------------------------------------------
// k_prep: Ft[b][n][c] = feat[b][c][n], bf16 hi/lo. grid (128,8,8), block (32,8)
// ---------------------------------------------------------------------------
__global__ void k_prep(const float* __restrict__ feat) {
    __shared__ float t[32][33];
    const int b = blockIdx.z, c0 = blockIdx.y * 32, n0 = blockIdx.x * 32;
    const int tx = threadIdx.x, ty = threadIdx.y;
    const float* F = feat + ((size_t)b * CC + c0) * NN + n0;
#pragma unroll
    for (int i = 0; i < 4; i++) t[ty + i * 8][tx] = F[(ty + i * 8) * NN + tx];
    __syncthreads();
#pragma unroll
    for (int i = 0; i < 4; i++) {
        int nr = ty + i * 8;
        float x = t[tx][nr];
        size_t o = ((size_t)b * NN + n0 + nr) * CC + c0 + tx;
        __nv_bfloat16 h = __float2bfloat16(x);
        g_Ft_hi[o] = h;
        g_Ft_lo[o] = __float2bfloat16(x - __bfloat162float(h));
    }
}

// ---------------------------------------------------------------------------
// k_z_mma: Zt[b][m][c] = sum_e Ft[m][e] * G[c][e].  grid (32, 8), 256 thr.
// ---------------------------------------------------------------------------
__global__ void __launch_bounds__(256, 1) k_z_mma() {
    extern __shared__ char sm[];
    const uint32_t smb = smem_u32(sm);
    const int tid = threadIdx.x, wid = tid >> 5, lane = tid & 31;
    const int m0 = blockIdx.x * 128, b = blockIdx.y;
    const int wr = wid & 3, wc = wid >> 2;
    const int l15 = lane & 15;
    const uint32_t lhi = (uint32_t)((lane >> 4) * 16);
    const uint32_t xorv = (uint32_t)((lane & 7) * 16);
    const uint32_t aro0 = (uint32_t)((wr * 32 + l15) * 128);
    uint32_t bro[4];
#pragma unroll
    for (int g16 = 0; g16 < 4; g16++) bro[g16] = (uint32_t)((wc * 64 + g16 * 16 + l15) * 128);

    // kick off B chunk t=0 (ch=0,kc=0)
    cpa_chunk(smb + OFF_B, g_Gk_hi, tid);
    cpa_chunk(smb + OFF_B + CH, g_Gk_lo, tid);
    CPA_COMMIT();

    // resident A: Ft rows m0..m0+127, hi/lo
    const __nv_bfloat16* Fh = g_Ft_hi + ((size_t)b * NN + m0) * CC;
    const __nv_bfloat16* Fl = g_Ft_lo + ((size_t)b * NN + m0) * CC;
#pragma unroll
    for (int cb = 0; cb < 8; cb++) {
        int p = cb >> 2, kc = cb & 3;
        copy_chunk(sm, OFF_A + cb * CH, (p ? Fl : Fh) + kc * 64, tid);
    }
    __syncthreads();

    for (int ch = 0; ch < 2; ch++) {
        float acc[2][8][4];
#pragma unroll
        for (int a = 0; a < 2; a++)
#pragma unroll
            for (int g = 0; g < 8; g++)
#pragma unroll
                for (int q = 0; q < 4; q++) acc[a][g][q] = 0.f;

#pragma unroll 1
        for (int kc = 0; kc < 4; kc++) {
            const int t = ch * 4 + kc;
            CPA_WAIT0();
            __syncthreads();
            // prefetch t+1
            if (t + 1 < 8) {
                int ch2 = (t + 1) >> 2, kc2 = (t + 1) & 3;
                uint32_t d = smb + OFF_B + ((t + 1) & 1) * BUFSZ;
                cpa_chunk(d, g_Gk_hi + (ch2 * 128) * CC + kc2 * 64, tid);
                cpa_chunk(d + CH, g_Gk_lo + (ch2 * 128) * CC + kc2 * 64, tid);
            }
            CPA_COMMIT();
            uint32_t bq = smb + OFF_B + (t & 1) * BUFSZ;
            mma_kchunk(smb + OFF_A + kc * CH, smb + OFF_A + (4 + kc) * CH,
                       bq, bq + CH, aro0, bro, lhi, xorv, acc);
        }

        // epilogue: split & store Zt hi/lo
        const int g8 = lane >> 2, tig = lane & 3;
#pragma unroll
        for (int a = 0; a < 2; a++)
#pragma unroll
            for (int h = 0; h < 2; h++) {
                const int r = wr * 32 + a * 16 + h * 8 + g8;
                size_t rowoff = ((size_t)b * NN + m0 + r) * CC + ch * 128;
#pragma unroll
                for (int g = 0; g < 8; g++) {
                    const int cl = wc * 64 + g * 8 + tig * 2;
                    float x0 = acc[a][g][h * 2], x1 = acc[a][g][h * 2 + 1];
                    __nv_bfloat16 h0 = __float2bfloat16(x0), h1 = __float2bfloat16(x1);
                    __nv_bfloat16 l0 = __float2bfloat16(x0 - __bfloat162float(h0));
                    __nv_bfloat16 l1 = __float2bfloat16(x1 - __bfloat162float(h1));
                    *(__nv_bfloat162*)(g_Zt_hi + rowoff + cl) = __nv_bfloat162(h0, h1);
                    *(__nv_bfloat162*)(g_Zt_lo + rowoff + cl) = __nv_bfloat162(l0, l1);
                }
            }
    }
}

// ---------------------------------------------------------------------------
// k_attn_mma: streaming S = Ft·Zt^T, online softmax diagonal, out = feat*diag.
// grid (32, 8), 256 thr.
// ---------------------------------------------------------------------------
__global__ void __launch_bounds__(256, 1) k_attn_mma(const float* __restrict__ feat,
                                                     float* __restrict__ out) {
    extern __shared__ char sm[];
    const uint32_t smb = smem_u32(sm);
    const int tid = threadIdx.x, wid = tid >> 5, lane = tid & 31;
    const int n0 = blockIdx.x * 128, b = blockIdx.y;
    const int wr = wid & 3, wc = wid >> 2;
    const int l15 = lane & 15;
    const uint32_t lhi = (uint32_t)((lane >> 4) * 16);
    const uint32_t xorv = (uint32_t)((lane & 7) * 16);
    const uint32_t aro0 = (uint32_t)((wr * 32 + l15) * 128);
    uint32_t bro[4];
#pragma unroll
    for (int g16 = 0; g16 < 4; g16++) bro[g16] = (uint32_t)((wc * 64 + g16 * 16 + l15) * 128);

    float* runm = (float*)(sm + EP_RUNM);
    float* runl = (float*)(sm + EP_RUNL);
    float* redA = (float*)(sm + EP_REDA);
    float* redB = (float*)(sm + EP_REDB);
    float* newm = (float*)(sm + EP_NEWM);
    float* dlog = (float*)(sm + EP_DLOG);
    float* diag = (float*)(sm + EP_DIAG);

    const __nv_bfloat16* Zh = g_Zt_hi + (size_t)b * NN * CC;
    const __nv_bfloat16* Zl = g_Zt_lo + (size_t)b * NN * CC;

    // kick off B chunk t=0
    cpa_chunk(smb + OFF_B, Zh, tid);
    cpa_chunk(smb + OFF_B + CH, Zl, tid);
    CPA_COMMIT();

    // resident A: Ft rows n0..n0+127
    const __nv_bfloat16* Fh = g_Ft_hi + ((size_t)b * NN + n0) * CC;
    const __nv_bfloat16* Fl = g_Ft_lo + ((size_t)b * NN + n0) * CC;
#pragma unroll
    for (int cb = 0; cb < 8; cb++) {
        int p = cb >> 2, kc = cb & 3;
        copy_chunk(sm, OFF_A + cb * CH, (p ? Fl : Fh) + kc * 64, tid);
    }
    if (tid < 128) { runm[tid] = -CUDART_INF_F; runl[tid] = 0.f; }
    __syncthreads();

    const int g8 = lane >> 2, tig = lane & 3;

#pragma unroll 1
    for (int mt = 0; mt < 32; mt++) {
        float acc[2][8][4];
#pragma unroll
        for (int a = 0; a < 2; a++)
#pragma unroll
            for (int g = 0; g < 8; g++)
#pragma unroll
                for (int q = 0; q < 4; q++) acc[a][g][q] = 0.f;

#pragma unroll 1
        for (int kc = 0; kc < 4; kc++) {
            const int t = mt * 4 + kc;
            CPA_WAIT0();
            __syncthreads();
            if (t + 1 < 128) {
                int mt2 = (t + 1) >> 2, kc2 = (t + 1) & 3;
                uint32_t d = smb + OFF_B + ((t + 1) & 1) * BUFSZ;
                cpa_chunk(d, Zh + (size_t)(mt2 * 128) * CC + kc2 * 64, tid);
                cpa_chunk(d + CH, Zl + (size_t)(mt2 * 128) * CC + kc2 * 64, tid);
            }
            CPA_COMMIT();
            uint32_t bq = smb + OFF_B + (t & 1) * BUFSZ;
            mma_kchunk(smb + OFF_A + kc * CH, smb + OFF_A + (4 + kc) * CH,
                       bq, bq + CH, aro0, bro, lhi, xorv, acc);
        }

        // ---- online softmax over this 128-col tile ----
#pragma unroll
        for (int a = 0; a < 2; a++)
#pragma unroll
            for (int h = 0; h < 2; h++) {
                const int rl = wr * 32 + a * 16 + h * 8 + g8;
                float mx = -CUDART_INF_F;
#pragma unroll
                for (int g = 0; g < 8; g++)
                    mx = fmaxf(mx, fmaxf(acc[a][g][h * 2], acc[a][g][h * 2 + 1]));
                mx = fmaxf(mx, __shfl_xor_sync(0xffffffffu, mx, 1));
                mx = fmaxf(mx, __shfl_xor_sync(0xffffffffu, mx, 2));
                if (tig == 0) redA[wc * 128 + rl] = mx;
            }
        __syncthreads();
        if (tid < 128) {
            float om = runm[tid];
            float nm = fmaxf(om, fmaxf(redA[tid], redA[128 + tid]));
            runl[tid] *= __expf(om - nm);
            runm[tid] = nm;
            newm[tid] = nm;
        }
        __syncthreads();
#pragma unroll
        for (int a = 0; a < 2; a++)
#pragma unroll
            for (int h = 0; h < 2; h++) {
                const int rl = wr * 32 + a * 16 + h * 8 + g8;
                const float nm = newm[rl];
                float s = 0.f;
#pragma unroll
                for (int g = 0; g < 8; g++) {
                    s += __expf(acc[a][g][h * 2] - nm);
                    s += __expf(acc[a][g][h * 2 + 1] - nm);
                }
                s += __shfl_xor_sync(0xffffffffu, s, 1);
                s += __shfl_xor_sync(0xffffffffu, s, 2);
                if (tig == 0) redB[wc * 128 + rl] = s;
            }
        __syncthreads();
        if (tid < 128) runl[tid] += redB[tid] + redB[128 + tid];

        if (mt == blockIdx.x) {  // diagonal tile: capture raw logit l_nn
#pragma unroll
            for (int a = 0; a < 2; a++)
#pragma unroll
                for (int h = 0; h < 2; h++) {
                    const int rl = wr * 32 + a * 16 + h * 8 + g8;
#pragma unroll
                    for (int g = 0; g < 8; g++)
#pragma unroll
                        for (int j = 0; j < 2; j++) {
                            const int cl = wc * 64 + g * 8 + tig * 2 + j;
                            if (cl == rl) dlog[rl] = acc[a][g][h * 2 + j];
                        }
                }
        }
        // next iteration's CPA_WAIT0+__syncthreads orders everything
    }

    __syncthreads();
    if (tid < 128) diag[tid] = __expf(dlog[tid] - runm[tid]) / runl[tid];
    __syncthreads();

    const float* F = feat + (size_t)b * CC * NN;
    float* O = out + (size_t)b * CC * NN;
    for (int u = tid; u < CC * 32; u += 256) {
        int c = u >> 5, seg = u & 31;
        float4 f = *(const float4*)(F + (size_t)c * NN + n0 + seg * 4);
        float4 o;
        o.x = f.x * diag[seg * 4 + 0];
        o.y = f.y * diag[seg * 4 + 1];
        o.z = f.z * diag[seg * 4 + 2];
        o.w = f.w * diag[seg * 4 + 3];
        *(float4*)(O + (size_t)c * NN + n0 + seg * 4) = o;
    }
}

// ---------------------------------------------------------------------------
extern "C" void kernel_launch(void* const* d_in, const int* in_sizes, int n_in,
                              void* d_out, int out_size) {
    const float* feat = (const float*)d_in[0];  // [B,C,N]
    const float* Wq   = (const float*)d_in[1];  // [C,C]
    const float* Wk   = (const float*)d_in[2];  // [C,C]
    float* out = (float*)d_out;                 // [B,C,N]

    cudaFuncSetAttribute(k_z_mma, cudaFuncAttributeMaxDynamicSharedMemorySize, SMEM_TOTAL);
    cudaFuncSetAttribute(k_attn_mma, cudaFuncAttributeMaxDynamicSharedMemorySize, SMEM_TOTAL);

    k_gt<<<CC / 2, CC>>>(Wq, Wk);
    k_prep<<<dim3(NN / 32, CC / 32, BB), dim3(32, 8)>>>(feat);
    k_z_mma<<<dim3(NN / 128, BB), 256, SMEM_TOTAL>>>();
    k_attn_mma<<<dim3(NN / 128, BB), 256, SMEM_TOTAL>>>(feat, out);
}